// round 10
// baseline (speedup 1.0000x reference)
#include <cuda_runtime.h>
#include <cuda_fp16.h>
#include <cstdint>

#define M_TOK 8192
#define D_DIM 2048
#define H_DIM 8192

// device-global scratch
__device__ __half g_x1h[(size_t)M_TOK * D_DIM];   // x1 -> half
__device__ __half g_x2h[(size_t)M_TOK * H_DIM];   // relu(y1) in half
__device__ __half g_wh [(size_t)H_DIM * D_DIM];   // dequantized weights (reused)
__device__ __half g_lbt[(size_t)H_DIM * 64];      // LB^T padded [N,64]
__device__ __half g_lat[16 * (size_t)H_DIM];      // lora_a^T [16,K]
__device__ __half g_tsh[(size_t)M_TOK * 64];      // T padded [M,64]
__device__ float  g_tp [8 * (size_t)M_TOK * 16];

// ---------------------------------------------------------------------------
__device__ __forceinline__ void ldm4(uint32_t* r, uint32_t addr) {
    asm volatile("ldmatrix.sync.aligned.m8n8.x4.shared.b16 {%0,%1,%2,%3}, [%4];"
                 : "=r"(r[0]), "=r"(r[1]), "=r"(r[2]), "=r"(r[3]) : "r"(addr));
}
__device__ __forceinline__ void mma16816(float* d, const uint32_t* a,
                                         uint32_t b0, uint32_t b1) {
    asm volatile("mma.sync.aligned.m16n8k16.row.col.f32.f16.f16.f32 "
                 "{%0,%1,%2,%3}, {%4,%5,%6,%7}, {%8,%9}, {%0,%1,%2,%3};"
                 : "+f"(d[0]), "+f"(d[1]), "+f"(d[2]), "+f"(d[3])
                 : "r"(a[0]), "r"(a[1]), "r"(a[2]), "r"(a[3]), "r"(b0), "r"(b1));
}
__device__ __forceinline__ void cp16(uint32_t dst, const void* src) {
    asm volatile("cp.async.cg.shared.global [%0], [%1], 16;" :: "r"(dst), "l"(src));
}

// ---------------------------------------------------------------------------
// prepasses
// ---------------------------------------------------------------------------
__global__ __launch_bounds__(256) void cvt_x(const float* __restrict__ in,
                                             __half* __restrict__ out)
{
    size_t i = ((size_t)blockIdx.x * 256 + threadIdx.x) * 8;
    float4 a = *(const float4*)(in + i);
    float4 b = *(const float4*)(in + i + 4);
    __half2 h[4] = {__floats2half2_rn(a.x, a.y), __floats2half2_rn(a.z, a.w),
                    __floats2half2_rn(b.x, b.y), __floats2half2_rn(b.z, b.w)};
    *(uint4*)(out + i) = *(uint4*)h;
}

__global__ __launch_bounds__(256) void dq_w(const int* __restrict__ Wq,
                                            const float* __restrict__ Wsc,
                                            __half* __restrict__ Wh, int K)
{
    size_t i8 = (size_t)blockIdx.x * 256 + threadIdx.x;
    const int K8 = K >> 3;
    int row = (int)(i8 / K8), k8 = (int)(i8 % K8);
    float s = Wsc[(size_t)row * (K >> 6) + (k8 >> 3)];
    int4 q0 = ((const int4*)Wq)[i8 * 2];
    int4 q1 = ((const int4*)Wq)[i8 * 2 + 1];
    __half2 h[4] = {
        __floats2half2_rn(((float)q0.x - 7.5f) * s, ((float)q0.y - 7.5f) * s),
        __floats2half2_rn(((float)q0.z - 7.5f) * s, ((float)q0.w - 7.5f) * s),
        __floats2half2_rn(((float)q1.x - 7.5f) * s, ((float)q1.y - 7.5f) * s),
        __floats2half2_rn(((float)q1.z - 7.5f) * s, ((float)q1.w - 7.5f) * s)};
    *(uint4*)(Wh + i8 * 8) = *(uint4*)h;
}

__global__ __launch_bounds__(256) void tr_lb(const float* __restrict__ LB,
                                             __half* __restrict__ LBT, int NT)
{   // LBT[n][r] = LB[r][n] for r<16, 0 for 16<=r<64
    int n = blockIdx.x * 256 + threadIdx.x;
    __half2 h[32];
#pragma unroll
    for (int r = 0; r < 8; r++)
        h[r] = __floats2half2_rn(LB[(size_t)(2 * r) * NT + n],
                                 LB[(size_t)(2 * r + 1) * NT + n]);
#pragma unroll
    for (int r = 8; r < 32; r++) h[r] = __floats2half2_rn(0.f, 0.f);
#pragma unroll
    for (int c = 0; c < 8; c++)
        *(uint4*)(LBT + (size_t)n * 64 + c * 8) = ((uint4*)h)[c];
}

// lora_a [K,16] float -> At [16,K] half (coalesced via smem transpose)
__global__ __launch_bounds__(256) void cvt_la(const float* __restrict__ A,
                                              __half* __restrict__ At, int K)
{
    __shared__ __half s[16][264];
    const int tid = threadIdx.x;
    const int k0 = blockIdx.x * 256;
#pragma unroll
    for (int q = 0; q < 4; q++) {
        float4 v = *(const float4*)(A + (size_t)(k0 + tid) * 16 + q * 4);
        s[q * 4 + 0][tid] = __float2half_rn(v.x);
        s[q * 4 + 1][tid] = __float2half_rn(v.y);
        s[q * 4 + 2][tid] = __float2half_rn(v.z);
        s[q * 4 + 3][tid] = __float2half_rn(v.w);
    }
    __syncthreads();
#pragma unroll
    for (int rep = 0; rep < 2; rep++) {
        int idx = tid + 256 * rep;
        int r = idx >> 5, c = idx & 31;
        *(uint4*)(At + (size_t)r * K + k0 + c * 8) = *(uint4*)&s[r][c * 8];
    }
}

// ---------------------------------------------------------------------------
// LoRA via tensor core (R9-proven): Tp[split][m][r] = X @ At^T on a k-chunk
// ---------------------------------------------------------------------------
__global__ __launch_bounds__(256) void lora_mma(const __half* __restrict__ X,
                                                const __half* __restrict__ At,
                                                float* __restrict__ Tp,
                                                int K, int KC)
{
    constexpr int PITCH = 80;
    constexpr int XSZ = 128 * PITCH;
    constexpr int BSZ = 16 * PITCH;
    constexpr int STG = XSZ + BSZ;
    constexpr int NST = 4;
    __shared__ __align__(16) char smem[NST * STG];
    uint32_t sbase;
    asm("{ .reg .u64 t; cvta.to.shared.u64 t, %1; cvt.u32.u64 %0, t; }"
        : "=r"(sbase) : "l"(smem));

    const int tid = threadIdx.x, lane = tid & 31, w = tid >> 5;
    const int lr = lane >> 2, lc = lane & 3;
    const int m0 = blockIdx.x * 128;
    const int k0 = blockIdx.y * KC;
    const int TOT = KC / 32;

    const int frow = tid >> 1;
    const int fc0 = (tid & 1) * 2;

    auto FILL = [&](int it) {
        if (it < TOT) {
            const uint32_t st = sbase + (uint32_t)(it & (NST - 1)) * STG;
            const int k = k0 + it * 32;
#pragma unroll
            for (int j = 0; j < 2; j++) {
                int c = fc0 + j;
                cp16(st + (uint32_t)(frow * PITCH + c * 16),
                     X + (size_t)(m0 + frow) * K + k + c * 8);
            }
            if (tid < 64) {
                int r = tid >> 2, c = tid & 3;
                cp16(st + (uint32_t)(XSZ + r * PITCH + c * 16),
                     At + (size_t)r * K + k + c * 8);
            }
        }
        asm volatile("cp.async.commit_group;" ::: "memory");
    };

    float acc[2][4];
#pragma unroll
    for (int i = 0; i < 2; i++)
#pragma unroll
        for (int j = 0; j < 4; j++) acc[i][j] = 0.f;

#pragma unroll
    for (int p = 0; p < NST - 1; ++p) FILL(p);

    const int arow = w * 16 + (lane & 15);
    const int asel = lane >> 4;
    const int brow = ((lane >> 4) << 3) + (lane & 7);
    const int bsel = (lane >> 3) & 1;

    for (int it = 0; it < TOT; ++it) {
        asm volatile("cp.async.wait_group %0;" :: "n"(NST - 2) : "memory");
        __syncthreads();
        const uint32_t sA = sbase + (uint32_t)(it & (NST - 1)) * STG;
        const uint32_t sB = sA + XSZ;
#pragma unroll
        for (int ks = 0; ks < 2; ks++) {
            uint32_t a[4], b[4];
            ldm4(a, sA + (uint32_t)(arow * PITCH + (ks * 2 + asel) * 16));
            ldm4(b, sB + (uint32_t)(brow * PITCH + (ks * 2 + bsel) * 16));
            mma16816(acc[0], a, b[0], b[1]);
            mma16816(acc[1], a, b[2], b[3]);
        }
        FILL(it + NST - 1);
    }

    float* o = Tp + (size_t)blockIdx.y * (M_TOK * 16);
    const int m = m0 + 16 * w + lr;
#pragma unroll
    for (int nt = 0; nt < 2; nt++) {
        const int col = 8 * nt + 2 * lc;
        *(float2*)(o + (size_t)m * 16 + col)       = make_float2(acc[nt][0], acc[nt][1]);
        *(float2*)(o + (size_t)(m + 8) * 16 + col) = make_float2(acc[nt][2], acc[nt][3]);
    }
}

__global__ __launch_bounds__(256) void lora_sum(const float* __restrict__ Tp,
                                                __half* __restrict__ Ts, int split)
{   // Ts padded to 64 cols: data in 0-15, zeros in 16-63
    const int i = blockIdx.x * 256 + threadIdx.x;
    const int m = i >> 2, rq = i & 3;
    const float4* p = (const float4*)Tp;
    float4 a = p[i];
    for (int s = 1; s < split; s++) {
        float4 b = p[i + (size_t)s * 32768];
        a.x += b.x; a.y += b.y; a.z += b.z; a.w += b.w;
    }
    __half2 h[2] = {__floats2half2_rn(a.x, a.y), __floats2half2_rn(a.z, a.w)};
    *(uint2*)(Ts + (size_t)m * 64 + rq * 4) = *(uint2*)h;
#pragma unroll
    for (int z = 0; z < 3; z++)
        *(uint2*)(Ts + (size_t)m * 64 + 16 + rq * 12 + z * 4) = make_uint2(0u, 0u);
}

// ---------------------------------------------------------------------------
// fp16 mma GEMM: CTA 128x128, BK=64, 256 thr, 3-stage cp.async, pitch-144.
// LoRA folded as one extra (zero-padded) k-tile.
// ---------------------------------------------------------------------------
template<bool RELU, bool STORE_HALF, int KTILES, int NT, int GROUP>
__global__ __launch_bounds__(256, 2) void gemm16(
    const __half* __restrict__ Xh, const __half* __restrict__ Wh,
    const float* __restrict__ bias,
    const __half* __restrict__ Tsh, const __half* __restrict__ LBTh,
    float* __restrict__ Yf, __half* __restrict__ Yh)
{
    constexpr int K   = KTILES * 64;
    constexpr int NTILES = NT / 128;
    constexpr int TOT = KTILES + 1;
    constexpr int PITCH = 144;            // 64 halves + 16B pad
    constexpr int ASZ = 128 * PITCH;      // 18432
    constexpr int STG = 2 * ASZ;          // 36864
    constexpr int NST = 3;

    extern __shared__ __align__(16) char smem[];
    float* sbias = (float*)(smem + NST * STG);
    uint32_t sbase;
    asm("{ .reg .u64 t; cvta.to.shared.u64 t, %1; cvt.u32.u64 %0, t; }"
        : "=r"(sbase) : "l"(smem));

    const int tid  = threadIdx.x;
    const int lane = tid & 31;
    const int wid  = tid >> 5;
    const int wm = wid & 3, wn = wid >> 2;
    const int lr = lane >> 2, lc = lane & 3;

    constexpr int NPG = GROUP * NTILES;
    const int pid = blockIdx.x;
    const int grp = pid / NPG, rem = pid % NPG;
    const int bm0 = (grp * GROUP + rem % GROUP) * 128;
    const int bn0 = (rem / GROUP) * 128;

    if (tid < 128) sbias[tid] = bias[bn0 + tid];

    const int frow = tid >> 1;            // 0..127
    const int fc0  = (tid & 1) * 4;       // 4 chunks of 16B

    auto FILL = [&](int it) {
        if (it < TOT) {
            const uint32_t st = sbase + (uint32_t)(it % NST) * STG;
            const bool mn = (it < KTILES);
            const int k0 = it * 64;
#pragma unroll
            for (int c = fc0; c < fc0 + 4; c++) {
                const __half* ga = mn ? Xh + (size_t)(bm0 + frow) * K + k0 + c * 8
                                      : Tsh + (size_t)(bm0 + frow) * 64 + c * 8;
                const __half* gb = mn ? Wh + (size_t)(bn0 + frow) * K + k0 + c * 8
                                      : LBTh + (size_t)(bn0 + frow) * 64 + c * 8;
                cp16(st + (uint32_t)(frow * PITCH + c * 16), ga);
                cp16(st + (uint32_t)(ASZ + frow * PITCH + c * 16), gb);
            }
        }
        asm volatile("cp.async.commit_group;" ::: "memory");
    };

    float acc[2][8][4];
#pragma unroll
    for (int i = 0; i < 2; i++)
#pragma unroll
        for (int j = 0; j < 8; j++)
#pragma unroll
            for (int k = 0; k < 4; k++) acc[i][j][k] = 0.f;

#pragma unroll
    for (int p = 0; p < NST - 1; ++p) FILL(p);

    const int arow = wm * 32 + (lane & 15);
    const int asel = lane >> 4;
    const int brow = wn * 64 + ((lane >> 4) << 3) + (lane & 7);
    const int bsel = (lane >> 3) & 1;

    for (int it = 0; it < TOT; ++it) {
        asm volatile("cp.async.wait_group %0;" :: "n"(NST - 2) : "memory");
        __syncthreads();

        FILL(it + NST - 1);   // issue next tile's loads before compute

        const uint32_t sA = sbase + (uint32_t)(it % NST) * STG;
        const uint32_t sB = sA + ASZ;
#pragma unroll
        for (int ks = 0; ks < 4; ks++) {
            uint32_t a[2][4];
#pragma unroll
            for (int mt = 0; mt < 2; mt++)
                ldm4(a[mt], sA + (uint32_t)((arow + mt * 16) * PITCH
                                            + (ks * 2 + asel) * 16));
#pragma unroll
            for (int np = 0; np < 4; np++) {
                uint32_t b[4];
                ldm4(b, sB + (uint32_t)((brow + np * 16) * PITCH
                                        + (ks * 2 + bsel) * 16));
#pragma unroll
                for (int mt = 0; mt < 2; mt++) {
                    mma16816(acc[mt][2 * np],     a[mt], b[0], b[1]);
                    mma16816(acc[mt][2 * np + 1], a[mt], b[2], b[3]);
                }
            }
        }
    }

#pragma unroll
    for (int mt = 0; mt < 2; mt++) {
        const int m = bm0 + 32 * wm + 16 * mt + lr;
#pragma unroll
        for (int nt = 0; nt < 8; nt++) {
            const int ncol = 64 * wn + 8 * nt + 2 * lc;
            const float b0 = sbias[ncol], b1 = sbias[ncol + 1];
            float v0 = acc[mt][nt][0] + b0, v1 = acc[mt][nt][1] + b1;
            float v2 = acc[mt][nt][2] + b0, v3 = acc[mt][nt][3] + b1;
            if (RELU) {
                v0 = fmaxf(v0, 0.f); v1 = fmaxf(v1, 0.f);
                v2 = fmaxf(v2, 0.f); v3 = fmaxf(v3, 0.f);
            }
            if (STORE_HALF) {
                *(__half2*)(Yh + (size_t)m * NT + bn0 + ncol) =
                    __floats2half2_rn(v0, v1);
                *(__half2*)(Yh + (size_t)(m + 8) * NT + bn0 + ncol) =
                    __floats2half2_rn(v2, v3);
            } else {
                *(float2*)(Yf + (size_t)m * NT + bn0 + ncol)       = make_float2(v0, v1);
                *(float2*)(Yf + (size_t)(m + 8) * NT + bn0 + ncol) = make_float2(v2, v3);
            }
        }
    }
}

// ---------------------------------------------------------------------------
extern "C" void kernel_launch(void* const* d_in, const int* in_sizes, int n_in,
                              void* d_out, int out_size)
{
    const float* x1      = (const float*)d_in[0];
    const int*   w_up_q  = (const int*)  d_in[1];
    const float* w_up_sc = (const float*)d_in[2];
    const float* b_up    = (const float*)d_in[3];
    const float* w_up_la = (const float*)d_in[4];
    const float* w_up_lb = (const float*)d_in[5];
    const int*   w_dn_q  = (const int*)  d_in[6];
    const float* w_dn_sc = (const float*)d_in[7];
    const float* b_dn    = (const float*)d_in[8];
    const float* w_dn_la = (const float*)d_in[9];
    const float* w_dn_lb = (const float*)d_in[10];
    float*       out     = (float*)d_out;

    __half *x1h, *x2h, *wh, *lbt, *lat, *tsh;
    float *tp;
    cudaGetSymbolAddress((void**)&x1h, g_x1h);
    cudaGetSymbolAddress((void**)&x2h, g_x2h);
    cudaGetSymbolAddress((void**)&wh,  g_wh);
    cudaGetSymbolAddress((void**)&lbt, g_lbt);
    cudaGetSymbolAddress((void**)&lat, g_lat);
    cudaGetSymbolAddress((void**)&tsh, g_tsh);
    cudaGetSymbolAddress((void**)&tp,  g_tp);

    constexpr int SMEM = 3 * (2 * 128 * 144) + 512;   // 110592 + 512
    cudaFuncSetAttribute(gemm16<true, true, 32, H_DIM, 16>,
                         cudaFuncAttributeMaxDynamicSharedMemorySize, SMEM);
    cudaFuncSetAttribute(gemm16<false, false, 128, D_DIM, 32>,
                         cudaFuncAttributeMaxDynamicSharedMemorySize, SMEM);

    // ---- layer 1 ----
    cvt_x<<<(M_TOK * D_DIM / 8) / 256, 256>>>(x1, x1h);
    dq_w<<<((size_t)H_DIM * D_DIM / 8) / 256, 256>>>(w_up_q, w_up_sc, wh, D_DIM);
    tr_lb<<<H_DIM / 256, 256>>>(w_up_lb, lbt, H_DIM);
    cvt_la<<<D_DIM / 256, 256>>>(w_up_la, lat, D_DIM);
    lora_mma<<<dim3(M_TOK / 128, 4), 256>>>(x1h, lat, tp, D_DIM, D_DIM / 4);
    lora_sum<<<128, 256>>>(tp, tsh, 4);
    gemm16<true, true, 32, H_DIM, 16>
        <<<(M_TOK / 128) * (H_DIM / 128), 256, SMEM>>>(
        x1h, wh, b_up, tsh, lbt, nullptr, x2h);

    // ---- layer 2 ----
    dq_w<<<((size_t)D_DIM * H_DIM / 8) / 256, 256>>>(w_dn_q, w_dn_sc, wh, H_DIM);
    tr_lb<<<D_DIM / 256, 256>>>(w_dn_lb, lbt, D_DIM);
    cvt_la<<<H_DIM / 256, 256>>>(w_dn_la, lat, H_DIM);
    lora_mma<<<dim3(M_TOK / 128, 8), 256>>>(x2h, lat, tp, H_DIM, H_DIM / 8);
    lora_sum<<<128, 256>>>(tp, tsh, 8);
    gemm16<false, false, 128, D_DIM, 32>
        <<<(M_TOK / 128) * (D_DIM / 128), 256, SMEM>>>(
        x2h, wh, b_dn, tsh, lbt, out, nullptr);
}

// round 11
// speedup vs baseline: 1.2140x; 1.2140x over previous
#include <cuda_runtime.h>
#include <cuda_fp16.h>
#include <cstdint>

#define M_TOK 8192
#define D_DIM 2048
#define H_DIM 8192

// device-global scratch
__device__ __half g_x1h[(size_t)M_TOK * D_DIM];   // x1 -> half
__device__ __half g_x2h[(size_t)M_TOK * H_DIM];   // relu(y1) in half
__device__ __half g_wh1[(size_t)H_DIM * D_DIM];   // dequantized up weights
__device__ __half g_wh2[(size_t)D_DIM * H_DIM];   // dequantized down weights
__device__ __half g_lbt1[(size_t)H_DIM * 32];     // LB1^T padded [N,32]
__device__ __half g_lbt2[(size_t)H_DIM * 32];     // LB2^T padded [N,32] (oversized ok)
__device__ __half g_lat1[16 * (size_t)H_DIM];     // lora_a1^T [16,K] (oversized ok)
__device__ __half g_lat2[16 * (size_t)H_DIM];     // lora_a2^T [16,K]
__device__ __half g_tsh[(size_t)M_TOK * 32];      // T padded [M,32]
__device__ float  g_tp [8 * (size_t)M_TOK * 16];

// ---------------------------------------------------------------------------
__device__ __forceinline__ void ldm4(uint32_t* r, uint32_t addr) {
    asm volatile("ldmatrix.sync.aligned.m8n8.x4.shared.b16 {%0,%1,%2,%3}, [%4];"
                 : "=r"(r[0]), "=r"(r[1]), "=r"(r[2]), "=r"(r[3]) : "r"(addr));
}
__device__ __forceinline__ void mma16816(float* d, const uint32_t* a,
                                         uint32_t b0, uint32_t b1) {
    asm volatile("mma.sync.aligned.m16n8k16.row.col.f32.f16.f16.f32 "
                 "{%0,%1,%2,%3}, {%4,%5,%6,%7}, {%8,%9}, {%0,%1,%2,%3};"
                 : "+f"(d[0]), "+f"(d[1]), "+f"(d[2]), "+f"(d[3])
                 : "r"(a[0]), "r"(a[1]), "r"(a[2]), "r"(a[3]), "r"(b0), "r"(b1));
}
__device__ __forceinline__ void cp16(uint32_t dst, const void* src) {
    asm volatile("cp.async.cg.shared.global [%0], [%1], 16;" :: "r"(dst), "l"(src));
}

// ---------------------------------------------------------------------------
// fused prepass: blockIdx ranges -> cvt_x | dq_w | tr_lb | cvt_la
// ---------------------------------------------------------------------------
__global__ __launch_bounds__(256) void prep(
    const float* __restrict__ x, __half* __restrict__ xh, int nx,
    const int* __restrict__ wq, const float* __restrict__ wsc,
    __half* __restrict__ wh, int Kw, int nw,
    const float* __restrict__ lb, __half* __restrict__ lbt, int NT, int nlb,
    const float* __restrict__ la, __half* __restrict__ lat, int Kl, int nla)
{
    const int b = blockIdx.x;
    const int tid = threadIdx.x;

    if (b < nx) {                         // ---- x float -> half
        size_t i = ((size_t)b * 256 + tid) * 8;
        float4 a = *(const float4*)(x + i);
        float4 c = *(const float4*)(x + i + 4);
        __half2 h[4] = {__floats2half2_rn(a.x, a.y), __floats2half2_rn(a.z, a.w),
                        __floats2half2_rn(c.x, c.y), __floats2half2_rn(c.z, c.w)};
        *(uint4*)(xh + i) = *(uint4*)h;
    } else if (b < nx + nw) {             // ---- dequant weights -> half
        size_t i8 = (size_t)(b - nx) * 256 + tid;
        const int K8 = Kw >> 3;
        int row = (int)(i8 / K8), k8 = (int)(i8 % K8);
        float s = wsc[(size_t)row * (Kw >> 6) + (k8 >> 3)];
        int4 q0 = ((const int4*)wq)[i8 * 2];
        int4 q1 = ((const int4*)wq)[i8 * 2 + 1];
        __half2 h[4] = {
            __floats2half2_rn(((float)q0.x - 7.5f) * s, ((float)q0.y - 7.5f) * s),
            __floats2half2_rn(((float)q0.z - 7.5f) * s, ((float)q0.w - 7.5f) * s),
            __floats2half2_rn(((float)q1.x - 7.5f) * s, ((float)q1.y - 7.5f) * s),
            __floats2half2_rn(((float)q1.z - 7.5f) * s, ((float)q1.w - 7.5f) * s)};
        *(uint4*)(wh + i8 * 8) = *(uint4*)h;
    } else if (b < nx + nw + nlb) {       // ---- LB^T padded [N,32]
        int n = (b - nx - nw) * 256 + tid;
        __half2 h[16];
#pragma unroll
        for (int r = 0; r < 8; r++)
            h[r] = __floats2half2_rn(lb[(size_t)(2 * r) * NT + n],
                                     lb[(size_t)(2 * r + 1) * NT + n]);
#pragma unroll
        for (int r = 8; r < 16; r++) h[r] = __floats2half2_rn(0.f, 0.f);
#pragma unroll
        for (int c = 0; c < 4; c++)
            *(uint4*)(lbt + (size_t)n * 32 + c * 8) = ((uint4*)h)[c];
    } else {                              // ---- lora_a [K,16] -> At [16,K]
        __shared__ __half s[16][264];
        const int k0 = (b - nx - nw - nlb) * 256;
#pragma unroll
        for (int q = 0; q < 4; q++) {
            float4 v = *(const float4*)(la + (size_t)(k0 + tid) * 16 + q * 4);
            s[q * 4 + 0][tid] = __float2half_rn(v.x);
            s[q * 4 + 1][tid] = __float2half_rn(v.y);
            s[q * 4 + 2][tid] = __float2half_rn(v.z);
            s[q * 4 + 3][tid] = __float2half_rn(v.w);
        }
        __syncthreads();
#pragma unroll
        for (int rep = 0; rep < 2; rep++) {
            int idx = tid + 256 * rep;
            int r = idx >> 5, c = idx & 31;
            *(uint4*)(lat + (size_t)r * Kl + k0 + c * 8) = *(uint4*)&s[r][c * 8];
        }
    }
}

// ---------------------------------------------------------------------------
// LoRA via tensor core (R9-proven): Tp[split][m][r] = X @ At^T on a k-chunk
// ---------------------------------------------------------------------------
__global__ __launch_bounds__(256) void lora_mma(const __half* __restrict__ X,
                                                const __half* __restrict__ At,
                                                float* __restrict__ Tp,
                                                int K, int KC)
{
    constexpr int PITCH = 80;
    constexpr int XSZ = 128 * PITCH;
    constexpr int BSZ = 16 * PITCH;
    constexpr int STG = XSZ + BSZ;
    constexpr int NST = 4;
    __shared__ __align__(16) char smem[NST * STG];
    uint32_t sbase;
    asm("{ .reg .u64 t; cvta.to.shared.u64 t, %1; cvt.u32.u64 %0, t; }"
        : "=r"(sbase) : "l"(smem));

    const int tid = threadIdx.x, lane = tid & 31, w = tid >> 5;
    const int lr = lane >> 2, lc = lane & 3;
    const int m0 = blockIdx.x * 128;
    const int k0 = blockIdx.y * KC;
    const int TOT = KC / 32;

    const int frow = tid >> 1;
    const int fc0 = (tid & 1) * 2;

    auto FILL = [&](int it) {
        if (it < TOT) {
            const uint32_t st = sbase + (uint32_t)(it & (NST - 1)) * STG;
            const int k = k0 + it * 32;
#pragma unroll
            for (int j = 0; j < 2; j++) {
                int c = fc0 + j;
                cp16(st + (uint32_t)(frow * PITCH + c * 16),
                     X + (size_t)(m0 + frow) * K + k + c * 8);
            }
            if (tid < 64) {
                int r = tid >> 2, c = tid & 3;
                cp16(st + (uint32_t)(XSZ + r * PITCH + c * 16),
                     At + (size_t)r * K + k + c * 8);
            }
        }
        asm volatile("cp.async.commit_group;" ::: "memory");
    };

    float acc[2][4];
#pragma unroll
    for (int i = 0; i < 2; i++)
#pragma unroll
        for (int j = 0; j < 4; j++) acc[i][j] = 0.f;

#pragma unroll
    for (int p = 0; p < NST - 1; ++p) FILL(p);

    const int arow = w * 16 + (lane & 15);
    const int asel = lane >> 4;
    const int brow = ((lane >> 4) << 3) + (lane & 7);
    const int bsel = (lane >> 3) & 1;

    for (int it = 0; it < TOT; ++it) {
        asm volatile("cp.async.wait_group %0;" :: "n"(NST - 2) : "memory");
        __syncthreads();
        const uint32_t sA = sbase + (uint32_t)(it & (NST - 1)) * STG;
        const uint32_t sB = sA + XSZ;
#pragma unroll
        for (int ks = 0; ks < 2; ks++) {
            uint32_t a[4], b[4];
            ldm4(a, sA + (uint32_t)(arow * PITCH + (ks * 2 + asel) * 16));
            ldm4(b, sB + (uint32_t)(brow * PITCH + (ks * 2 + bsel) * 16));
            mma16816(acc[0], a, b[0], b[1]);
            mma16816(acc[1], a, b[2], b[3]);
        }
        FILL(it + NST - 1);
    }

    float* o = Tp + (size_t)blockIdx.y * (M_TOK * 16);
    const int m = m0 + 16 * w + lr;
#pragma unroll
    for (int nt = 0; nt < 2; nt++) {
        const int col = 8 * nt + 2 * lc;
        *(float2*)(o + (size_t)m * 16 + col)       = make_float2(acc[nt][0], acc[nt][1]);
        *(float2*)(o + (size_t)(m + 8) * 16 + col) = make_float2(acc[nt][2], acc[nt][3]);
    }
}

__global__ __launch_bounds__(256) void lora_sum(const float* __restrict__ Tp,
                                                __half* __restrict__ Ts, int split)
{
    const int i = blockIdx.x * 256 + threadIdx.x;
    const int m = i >> 2, rq = i & 3;
    const float4* p = (const float4*)Tp;
    float4 a = p[i];
    for (int s = 1; s < split; s++) {
        float4 b = p[i + (size_t)s * 32768];
        a.x += b.x; a.y += b.y; a.z += b.z; a.w += b.w;
    }
    __half2 h[2] = {__floats2half2_rn(a.x, a.y), __floats2half2_rn(a.z, a.w)};
    *(uint2*)(Ts + (size_t)m * 32 + rq * 4) = *(uint2*)h;
    *(uint2*)(Ts + (size_t)m * 32 + 16 + rq * 4) = make_uint2(0u, 0u);
}

// ---------------------------------------------------------------------------
// fp16 mma GEMM: CTA 128x128, BK=32, 256 thr, 5-stage cp.async ring,
// pitch-80 smem, FILL issued before compute, LoRA folded as one extra k-tile.
// ---------------------------------------------------------------------------
template<bool RELU, bool STORE_HALF, int KTILES, int NT, int GROUP>
__global__ __launch_bounds__(256, 2) void gemm16(
    const __half* __restrict__ Xh, const __half* __restrict__ Wh,
    const float* __restrict__ bias,
    const __half* __restrict__ Tsh, const __half* __restrict__ LBTh,
    float* __restrict__ Yf, __half* __restrict__ Yh)
{
    constexpr int K   = KTILES * 32;
    constexpr int NTILES = NT / 128;
    constexpr int TOT = KTILES + 1;
    constexpr int PITCH = 80;
    constexpr int ASZ = 128 * PITCH;
    constexpr int STG = 2 * ASZ;          // 20 KB
    constexpr int NST = 5;

    extern __shared__ __align__(16) char smem[];
    float* sbias = (float*)(smem + NST * STG);
    uint32_t sbase;
    asm("{ .reg .u64 t; cvta.to.shared.u64 t, %1; cvt.u32.u64 %0, t; }"
        : "=r"(sbase) : "l"(smem));

    const int tid  = threadIdx.x;
    const int lane = tid & 31;
    const int wid  = tid >> 5;
    const int wm = wid & 3, wn = wid >> 2;
    const int lr = lane >> 2, lc = lane & 3;

    constexpr int NPG = GROUP * NTILES;
    const int pid = blockIdx.x;
    const int grp = pid / NPG, rem = pid % NPG;
    const int bm0 = (grp * GROUP + rem % GROUP) * 128;
    const int bn0 = (rem / GROUP) * 128;

    if (tid < 128) sbias[tid] = bias[bn0 + tid];

    const int frow = tid >> 1;
    const int fc0  = (tid & 1) * 2;

    auto FILL = [&](int it) {
        if (it < TOT) {
            const uint32_t st = sbase + (uint32_t)(it % NST) * STG;
            const bool mn = (it < KTILES);
            const int k0 = it * 32;
#pragma unroll
            for (int c = fc0; c < fc0 + 2; c++) {
                const __half* ga = mn ? Xh + (size_t)(bm0 + frow) * K + k0 + c * 8
                                      : Tsh + (size_t)(bm0 + frow) * 32 + c * 8;
                const __half* gb = mn ? Wh + (size_t)(bn0 + frow) * K + k0 + c * 8
                                      : LBTh + (size_t)(bn0 + frow) * 32 + c * 8;
                cp16(st + (uint32_t)(frow * PITCH + c * 16), ga);
                cp16(st + (uint32_t)(ASZ + frow * PITCH + c * 16), gb);
            }
        }
        asm volatile("cp.async.commit_group;" ::: "memory");
    };

    float acc[2][8][4];
#pragma unroll
    for (int i = 0; i < 2; i++)
#pragma unroll
        for (int j = 0; j < 8; j++)
#pragma unroll
            for (int k = 0; k < 4; k++) acc[i][j][k] = 0.f;

#pragma unroll
    for (int p = 0; p < NST - 1; ++p) FILL(p);

    const int arow = wm * 32 + (lane & 15);
    const int asel = lane >> 4;
    const int brow = wn * 64 + ((lane >> 4) << 3) + (lane & 7);
    const int bsel = (lane >> 3) & 1;

    for (int it = 0; it < TOT; ++it) {
        asm volatile("cp.async.wait_group %0;" :: "n"(NST - 2) : "memory");
        __syncthreads();

        FILL(it + NST - 1);   // prefetch next before compute (stage reuse is safe)

        const uint32_t sA = sbase + (uint32_t)(it % NST) * STG;
        const uint32_t sB = sA + ASZ;
#pragma unroll
        for (int ks = 0; ks < 2; ks++) {
            uint32_t a[2][4];
#pragma unroll
            for (int mt = 0; mt < 2; mt++)
                ldm4(a[mt], sA + (uint32_t)((arow + mt * 16) * PITCH
                                            + (ks * 2 + asel) * 16));
#pragma unroll
            for (int np = 0; np < 4; np++) {
                uint32_t b[4];
                ldm4(b, sB + (uint32_t)((brow + np * 16) * PITCH
                                        + (ks * 2 + bsel) * 16));
#pragma unroll
                for (int mt = 0; mt < 2; mt++) {
                    mma16816(acc[mt][2 * np],     a[mt], b[0], b[1]);
                    mma16816(acc[mt][2 * np + 1], a[mt], b[2], b[3]);
                }
            }
        }
    }

#pragma unroll
    for (int mt = 0; mt < 2; mt++) {
        const int m = bm0 + 32 * wm + 16 * mt + lr;
#pragma unroll
        for (int nt = 0; nt < 8; nt++) {
            const int ncol = 64 * wn + 8 * nt + 2 * lc;
            const float b0 = sbias[ncol], b1 = sbias[ncol + 1];
            float v0 = acc[mt][nt][0] + b0, v1 = acc[mt][nt][1] + b1;
            float v2 = acc[mt][nt][2] + b0, v3 = acc[mt][nt][3] + b1;
            if (RELU) {
                v0 = fmaxf(v0, 0.f); v1 = fmaxf(v1, 0.f);
                v2 = fmaxf(v2, 0.f); v3 = fmaxf(v3, 0.f);
            }
            if (STORE_HALF) {
                *(__half2*)(Yh + (size_t)m * NT + bn0 + ncol) =
                    __floats2half2_rn(v0, v1);
                *(__half2*)(Yh + (size_t)(m + 8) * NT + bn0 + ncol) =
                    __floats2half2_rn(v2, v3);
            } else {
                *(float2*)(Yf + (size_t)m * NT + bn0 + ncol)       = make_float2(v0, v1);
                *(float2*)(Yf + (size_t)(m + 8) * NT + bn0 + ncol) = make_float2(v2, v3);
            }
        }
    }
}

// ---------------------------------------------------------------------------
extern "C" void kernel_launch(void* const* d_in, const int* in_sizes, int n_in,
                              void* d_out, int out_size)
{
    const float* x1      = (const float*)d_in[0];
    const int*   w_up_q  = (const int*)  d_in[1];
    const float* w_up_sc = (const float*)d_in[2];
    const float* b_up    = (const float*)d_in[3];
    const float* w_up_la = (const float*)d_in[4];
    const float* w_up_lb = (const float*)d_in[5];
    const int*   w_dn_q  = (const int*)  d_in[6];
    const float* w_dn_sc = (const float*)d_in[7];
    const float* b_dn    = (const float*)d_in[8];
    const float* w_dn_la = (const float*)d_in[9];
    const float* w_dn_lb = (const float*)d_in[10];
    float*       out     = (float*)d_out;

    __half *x1h, *x2h, *wh1, *wh2, *lbt1, *lbt2, *lat1, *lat2, *tsh;
    float *tp;
    cudaGetSymbolAddress((void**)&x1h,  g_x1h);
    cudaGetSymbolAddress((void**)&x2h,  g_x2h);
    cudaGetSymbolAddress((void**)&wh1,  g_wh1);
    cudaGetSymbolAddress((void**)&wh2,  g_wh2);
    cudaGetSymbolAddress((void**)&lbt1, g_lbt1);
    cudaGetSymbolAddress((void**)&lbt2, g_lbt2);
    cudaGetSymbolAddress((void**)&lat1, g_lat1);
    cudaGetSymbolAddress((void**)&lat2, g_lat2);
    cudaGetSymbolAddress((void**)&tsh,  g_tsh);
    cudaGetSymbolAddress((void**)&tp,   g_tp);

    constexpr int SMEM = 5 * (2 * 128 * 80) + 512;   // 102400 + 512
    cudaFuncSetAttribute(gemm16<true, true, 64, H_DIM, 16>,
                         cudaFuncAttributeMaxDynamicSharedMemorySize, SMEM);
    cudaFuncSetAttribute(gemm16<false, false, 256, D_DIM, 32>,
                         cudaFuncAttributeMaxDynamicSharedMemorySize, SMEM);

    constexpr int NW = (int)(((size_t)H_DIM * D_DIM / 8) / 256);  // 8192
    constexpr int NX = (int)((M_TOK * (size_t)D_DIM / 8) / 256);  // 8192

    // ---- fused prepasses (layer1 then layer2 weight/LoRA prep) ----
    prep<<<NX + NW + H_DIM / 256 + D_DIM / 256, 256>>>(
        x1, x1h, NX,
        w_up_q, w_up_sc, wh1, D_DIM, NW,
        w_up_lb, lbt1, H_DIM, H_DIM / 256,
        w_up_la, lat1, D_DIM, D_DIM / 256);
    prep<<<NW + D_DIM / 256 + H_DIM / 256, 256>>>(
        nullptr, nullptr, 0,
        w_dn_q, w_dn_sc, wh2, H_DIM, NW,
        w_dn_lb, lbt2, D_DIM, D_DIM / 256,
        w_dn_la, lat2, H_DIM, H_DIM / 256);

    // ---- layer 1 ----
    lora_mma<<<dim3(M_TOK / 128, 4), 256>>>(x1h, lat1, tp, D_DIM, D_DIM / 4);
    lora_sum<<<128, 256>>>(tp, tsh, 4);
    gemm16<true, true, 64, H_DIM, 16>
        <<<(M_TOK / 128) * (H_DIM / 128), 256, SMEM>>>(
        x1h, wh1, b_up, tsh, lbt1, nullptr, x2h);

    // ---- layer 2 ----
    lora_mma<<<dim3(M_TOK / 128, 8), 256>>>(x2h, lat2, tp, H_DIM, H_DIM / 8);
    lora_sum<<<128, 256>>>(tp, tsh, 8);
    gemm16<false, false, 256, D_DIM, 32>
        <<<(M_TOK / 128) * (D_DIM / 128), 256, SMEM>>>(
        x2h, wh2, b_dn, tsh, lbt2, out, nullptr);
}

// round 12
// speedup vs baseline: 1.3838x; 1.1398x over previous
#include <cuda_runtime.h>
#include <cuda_fp16.h>
#include <cstdint>

#define M_TOK 8192
#define D_DIM 2048
#define H_DIM 8192

// device-global scratch
__device__ __half g_x1h[(size_t)M_TOK * D_DIM];   // x1 -> half
__device__ __half g_x2h[(size_t)M_TOK * H_DIM];   // relu(y1) in half
__device__ __half g_wh1[(size_t)H_DIM * D_DIM];   // dequantized up weights
__device__ __half g_wh2[(size_t)D_DIM * H_DIM];   // dequantized down weights
__device__ __half g_lbt1[(size_t)H_DIM * 32];     // LB1^T padded [N,32]
__device__ __half g_lbt2[(size_t)H_DIM * 32];     // LB2^T padded [N,32]
__device__ __half g_lat1[16 * (size_t)H_DIM];     // lora_a1^T [16,K]
__device__ __half g_lat2[16 * (size_t)H_DIM];     // lora_a2^T [16,K]
__device__ __half g_tsh[(size_t)M_TOK * 32];      // T padded [M,32]
__device__ float  g_tp [8 * (size_t)M_TOK * 16];

// ---------------------------------------------------------------------------
__device__ __forceinline__ void ldm4(uint32_t* r, uint32_t addr) {
    asm volatile("ldmatrix.sync.aligned.m8n8.x4.shared.b16 {%0,%1,%2,%3}, [%4];"
                 : "=r"(r[0]), "=r"(r[1]), "=r"(r[2]), "=r"(r[3]) : "r"(addr));
}
__device__ __forceinline__ void mma16816(float* d, const uint32_t* a,
                                         uint32_t b0, uint32_t b1) {
    asm volatile("mma.sync.aligned.m16n8k16.row.col.f32.f16.f16.f32 "
                 "{%0,%1,%2,%3}, {%4,%5,%6,%7}, {%8,%9}, {%0,%1,%2,%3};"
                 : "+f"(d[0]), "+f"(d[1]), "+f"(d[2]), "+f"(d[3])
                 : "r"(a[0]), "r"(a[1]), "r"(a[2]), "r"(a[3]), "r"(b0), "r"(b1));
}
__device__ __forceinline__ void cp16(uint32_t dst, const void* src) {
    asm volatile("cp.async.cg.shared.global [%0], [%1], 16;" :: "r"(dst), "l"(src));
}

// ---------------------------------------------------------------------------
// fused prepass: blockIdx ranges -> cvt_x | dq_w | tr_lb | cvt_la
// ---------------------------------------------------------------------------
__global__ __launch_bounds__(256) void prep(
    const float* __restrict__ x, __half* __restrict__ xh, int nx,
    const int* __restrict__ wq, const float* __restrict__ wsc,
    __half* __restrict__ wh, int Kw, int nw,
    const float* __restrict__ lb, __half* __restrict__ lbt, int NT, int nlb,
    const float* __restrict__ la, __half* __restrict__ lat, int Kl, int nla)
{
    const int b = blockIdx.x;
    const int tid = threadIdx.x;

    if (b < nx) {                         // ---- x float -> half
        size_t i = ((size_t)b * 256 + tid) * 8;
        float4 a = *(const float4*)(x + i);
        float4 c = *(const float4*)(x + i + 4);
        __half2 h[4] = {__floats2half2_rn(a.x, a.y), __floats2half2_rn(a.z, a.w),
                        __floats2half2_rn(c.x, c.y), __floats2half2_rn(c.z, c.w)};
        *(uint4*)(xh + i) = *(uint4*)h;
    } else if (b < nx + nw) {             // ---- dequant weights -> half
        size_t i8 = (size_t)(b - nx) * 256 + tid;
        const int K8 = Kw >> 3;
        int row = (int)(i8 / K8), k8 = (int)(i8 % K8);
        float s = wsc[(size_t)row * (Kw >> 6) + (k8 >> 3)];
        int4 q0 = ((const int4*)wq)[i8 * 2];
        int4 q1 = ((const int4*)wq)[i8 * 2 + 1];
        __half2 h[4] = {
            __floats2half2_rn(((float)q0.x - 7.5f) * s, ((float)q0.y - 7.5f) * s),
            __floats2half2_rn(((float)q0.z - 7.5f) * s, ((float)q0.w - 7.5f) * s),
            __floats2half2_rn(((float)q1.x - 7.5f) * s, ((float)q1.y - 7.5f) * s),
            __floats2half2_rn(((float)q1.z - 7.5f) * s, ((float)q1.w - 7.5f) * s)};
        *(uint4*)(wh + i8 * 8) = *(uint4*)h;
    } else if (b < nx + nw + nlb) {       // ---- LB^T padded [N,32]
        int n = (b - nx - nw) * 256 + tid;
        __half2 h[16];
#pragma unroll
        for (int r = 0; r < 8; r++)
            h[r] = __floats2half2_rn(lb[(size_t)(2 * r) * NT + n],
                                     lb[(size_t)(2 * r + 1) * NT + n]);
#pragma unroll
        for (int r = 8; r < 16; r++) h[r] = __floats2half2_rn(0.f, 0.f);
#pragma unroll
        for (int c = 0; c < 4; c++)
            *(uint4*)(lbt + (size_t)n * 32 + c * 8) = ((uint4*)h)[c];
    } else {                              // ---- lora_a [K,16] -> At [16,K]
        __shared__ __half s[16][264];
        const int k0 = (b - nx - nw - nlb) * 256;
#pragma unroll
        for (int q = 0; q < 4; q++) {
            float4 v = *(const float4*)(la + (size_t)(k0 + tid) * 16 + q * 4);
            s[q * 4 + 0][tid] = __float2half_rn(v.x);
            s[q * 4 + 1][tid] = __float2half_rn(v.y);
            s[q * 4 + 2][tid] = __float2half_rn(v.z);
            s[q * 4 + 3][tid] = __float2half_rn(v.w);
        }
        __syncthreads();
#pragma unroll
        for (int rep = 0; rep < 2; rep++) {
            int idx = tid + 256 * rep;
            int r = idx >> 5, c = idx & 31;
            *(uint4*)(lat + (size_t)r * Kl + k0 + c * 8) = *(uint4*)&s[r][c * 8];
        }
    }
}

// ---------------------------------------------------------------------------
// LoRA via tensor core (R9-proven): Tp[split][m][r] = X @ At^T on a k-chunk
// ---------------------------------------------------------------------------
__global__ __launch_bounds__(256) void lora_mma(const __half* __restrict__ X,
                                                const __half* __restrict__ At,
                                                float* __restrict__ Tp,
                                                int K, int KC)
{
    constexpr int PITCH = 80;
    constexpr int XSZ = 128 * PITCH;
    constexpr int BSZ = 16 * PITCH;
    constexpr int STG = XSZ + BSZ;
    constexpr int NST = 4;
    __shared__ __align__(16) char smem[NST * STG];
    uint32_t sbase;
    asm("{ .reg .u64 t; cvta.to.shared.u64 t, %1; cvt.u32.u64 %0, t; }"
        : "=r"(sbase) : "l"(smem));

    const int tid = threadIdx.x, lane = tid & 31, w = tid >> 5;
    const int lr = lane >> 2, lc = lane & 3;
    const int m0 = blockIdx.x * 128;
    const int k0 = blockIdx.y * KC;
    const int TOT = KC / 32;

    const int frow = tid >> 1;
    const int fc0 = (tid & 1) * 2;

    auto FILL = [&](int it) {
        if (it < TOT) {
            const uint32_t st = sbase + (uint32_t)(it & (NST - 1)) * STG;
            const int k = k0 + it * 32;
#pragma unroll
            for (int j = 0; j < 2; j++) {
                int c = fc0 + j;
                cp16(st + (uint32_t)(frow * PITCH + c * 16),
                     X + (size_t)(m0 + frow) * K + k + c * 8);
            }
            if (tid < 64) {
                int r = tid >> 2, c = tid & 3;
                cp16(st + (uint32_t)(XSZ + r * PITCH + c * 16),
                     At + (size_t)r * K + k + c * 8);
            }
        }
        asm volatile("cp.async.commit_group;" ::: "memory");
    };

    float acc[2][4];
#pragma unroll
    for (int i = 0; i < 2; i++)
#pragma unroll
        for (int j = 0; j < 4; j++) acc[i][j] = 0.f;

#pragma unroll
    for (int p = 0; p < NST - 1; ++p) FILL(p);

    const int arow = w * 16 + (lane & 15);
    const int asel = lane >> 4;
    const int brow = ((lane >> 4) << 3) + (lane & 7);
    const int bsel = (lane >> 3) & 1;

    for (int it = 0; it < TOT; ++it) {
        asm volatile("cp.async.wait_group %0;" :: "n"(NST - 2) : "memory");
        __syncthreads();
        const uint32_t sA = sbase + (uint32_t)(it & (NST - 1)) * STG;
        const uint32_t sB = sA + XSZ;
#pragma unroll
        for (int ks = 0; ks < 2; ks++) {
            uint32_t a[4], b[4];
            ldm4(a, sA + (uint32_t)(arow * PITCH + (ks * 2 + asel) * 16));
            ldm4(b, sB + (uint32_t)(brow * PITCH + (ks * 2 + bsel) * 16));
            mma16816(acc[0], a, b[0], b[1]);
            mma16816(acc[1], a, b[2], b[3]);
        }
        FILL(it + NST - 1);
    }

    float* o = Tp + (size_t)blockIdx.y * (M_TOK * 16);
    const int m = m0 + 16 * w + lr;
#pragma unroll
    for (int nt = 0; nt < 2; nt++) {
        const int col = 8 * nt + 2 * lc;
        *(float2*)(o + (size_t)m * 16 + col)       = make_float2(acc[nt][0], acc[nt][1]);
        *(float2*)(o + (size_t)(m + 8) * 16 + col) = make_float2(acc[nt][2], acc[nt][3]);
    }
}

__global__ __launch_bounds__(256) void lora_sum(const float* __restrict__ Tp,
                                                __half* __restrict__ Ts, int split)
{
    const int i = blockIdx.x * 256 + threadIdx.x;
    const int m = i >> 2, rq = i & 3;
    const float4* p = (const float4*)Tp;
    float4 a = p[i];
    for (int s = 1; s < split; s++) {
        float4 b = p[i + (size_t)s * 32768];
        a.x += b.x; a.y += b.y; a.z += b.z; a.w += b.w;
    }
    __half2 h[2] = {__floats2half2_rn(a.x, a.y), __floats2half2_rn(a.z, a.w)};
    *(uint2*)(Ts + (size_t)m * 32 + rq * 4) = *(uint2*)h;
    *(uint2*)(Ts + (size_t)m * 32 + 16 + rq * 4) = make_uint2(0u, 0u);
}

// ---------------------------------------------------------------------------
// fp16 mma GEMM (R9-proven, frozen): CTA 128x128, BK=32, 256 thr,
// 4-stage cp.async ring, pitch-80 smem, LoRA folded as one extra k-tile.
// ---------------------------------------------------------------------------
template<bool RELU, bool STORE_HALF, int KTILES, int NT, int GROUP>
__global__ __launch_bounds__(256, 2) void gemm16(
    const __half* __restrict__ Xh, const __half* __restrict__ Wh,
    const float* __restrict__ bias,
    const __half* __restrict__ Tsh, const __half* __restrict__ LBTh,
    float* __restrict__ Yf, __half* __restrict__ Yh)
{
    constexpr int K   = KTILES * 32;
    constexpr int NTILES = NT / 128;
    constexpr int TOT = KTILES + 1;
    constexpr int PITCH = 80;
    constexpr int ASZ = 128 * PITCH;
    constexpr int STG = 2 * ASZ;
    constexpr int NST = 4;

    extern __shared__ __align__(16) char smem[];
    float* sbias = (float*)(smem + NST * STG);
    uint32_t sbase;
    asm("{ .reg .u64 t; cvta.to.shared.u64 t, %1; cvt.u32.u64 %0, t; }"
        : "=r"(sbase) : "l"(smem));

    const int tid  = threadIdx.x;
    const int lane = tid & 31;
    const int wid  = tid >> 5;
    const int wm = wid & 3, wn = wid >> 2;
    const int lr = lane >> 2, lc = lane & 3;

    constexpr int NPG = GROUP * NTILES;
    const int pid = blockIdx.x;
    const int grp = pid / NPG, rem = pid % NPG;
    const int bm0 = (grp * GROUP + rem % GROUP) * 128;
    const int bn0 = (rem / GROUP) * 128;

    if (tid < 128) sbias[tid] = bias[bn0 + tid];

    const int frow = tid >> 1;
    const int fc0  = (tid & 1) * 2;

    auto FILL = [&](int it) {
        if (it < TOT) {
            const uint32_t st = sbase + (uint32_t)(it % NST) * STG;
            const bool mn = (it < KTILES);
            const int k0 = it * 32;
#pragma unroll
            for (int c = fc0; c < fc0 + 2; c++) {
                const __half* ga = mn ? Xh + (size_t)(bm0 + frow) * K + k0 + c * 8
                                      : Tsh + (size_t)(bm0 + frow) * 32 + c * 8;
                const __half* gb = mn ? Wh + (size_t)(bn0 + frow) * K + k0 + c * 8
                                      : LBTh + (size_t)(bn0 + frow) * 32 + c * 8;
                cp16(st + (uint32_t)(frow * PITCH + c * 16), ga);
                cp16(st + (uint32_t)(ASZ + frow * PITCH + c * 16), gb);
            }
        }
        asm volatile("cp.async.commit_group;" ::: "memory");
    };

    float acc[2][8][4];
#pragma unroll
    for (int i = 0; i < 2; i++)
#pragma unroll
        for (int j = 0; j < 8; j++)
#pragma unroll
            for (int k = 0; k < 4; k++) acc[i][j][k] = 0.f;

#pragma unroll
    for (int p = 0; p < NST - 1; ++p) FILL(p);

    const int arow = wm * 32 + (lane & 15);
    const int asel = lane >> 4;
    const int brow = wn * 64 + ((lane >> 4) << 3) + (lane & 7);
    const int bsel = (lane >> 3) & 1;

    for (int it = 0; it < TOT; ++it) {
        asm volatile("cp.async.wait_group %0;" :: "n"(NST - 2) : "memory");
        __syncthreads();

        const uint32_t sA = sbase + (uint32_t)(it % NST) * STG;
        const uint32_t sB = sA + ASZ;
#pragma unroll
        for (int ks = 0; ks < 2; ks++) {
            uint32_t a[2][4];
#pragma unroll
            for (int mt = 0; mt < 2; mt++)
                ldm4(a[mt], sA + (uint32_t)((arow + mt * 16) * PITCH
                                            + (ks * 2 + asel) * 16));
#pragma unroll
            for (int np = 0; np < 4; np++) {
                uint32_t b[4];
                ldm4(b, sB + (uint32_t)((brow + np * 16) * PITCH
                                        + (ks * 2 + bsel) * 16));
#pragma unroll
                for (int mt = 0; mt < 2; mt++) {
                    mma16816(acc[mt][2 * np],     a[mt], b[0], b[1]);
                    mma16816(acc[mt][2 * np + 1], a[mt], b[2], b[3]);
                }
            }
        }
        FILL(it + NST - 1);
    }

#pragma unroll
    for (int mt = 0; mt < 2; mt++) {
        const int m = bm0 + 32 * wm + 16 * mt + lr;
#pragma unroll
        for (int nt = 0; nt < 8; nt++) {
            const int ncol = 64 * wn + 8 * nt + 2 * lc;
            const float b0 = sbias[ncol], b1 = sbias[ncol + 1];
            float v0 = acc[mt][nt][0] + b0, v1 = acc[mt][nt][1] + b1;
            float v2 = acc[mt][nt][2] + b0, v3 = acc[mt][nt][3] + b1;
            if (RELU) {
                v0 = fmaxf(v0, 0.f); v1 = fmaxf(v1, 0.f);
                v2 = fmaxf(v2, 0.f); v3 = fmaxf(v3, 0.f);
            }
            if (STORE_HALF) {
                *(__half2*)(Yh + (size_t)m * NT + bn0 + ncol) =
                    __floats2half2_rn(v0, v1);
                *(__half2*)(Yh + (size_t)(m + 8) * NT + bn0 + ncol) =
                    __floats2half2_rn(v2, v3);
            } else {
                *(float2*)(Yf + (size_t)m * NT + bn0 + ncol)       = make_float2(v0, v1);
                *(float2*)(Yf + (size_t)(m + 8) * NT + bn0 + ncol) = make_float2(v2, v3);
            }
        }
    }
}

// ---------------------------------------------------------------------------
extern "C" void kernel_launch(void* const* d_in, const int* in_sizes, int n_in,
                              void* d_out, int out_size)
{
    const float* x1      = (const float*)d_in[0];
    const int*   w_up_q  = (const int*)  d_in[1];
    const float* w_up_sc = (const float*)d_in[2];
    const float* b_up    = (const float*)d_in[3];
    const float* w_up_la = (const float*)d_in[4];
    const float* w_up_lb = (const float*)d_in[5];
    const int*   w_dn_q  = (const int*)  d_in[6];
    const float* w_dn_sc = (const float*)d_in[7];
    const float* b_dn    = (const float*)d_in[8];
    const float* w_dn_la = (const float*)d_in[9];
    const float* w_dn_lb = (const float*)d_in[10];
    float*       out     = (float*)d_out;

    __half *x1h, *x2h, *wh1, *wh2, *lbt1, *lbt2, *lat1, *lat2, *tsh;
    float *tp;
    cudaGetSymbolAddress((void**)&x1h,  g_x1h);
    cudaGetSymbolAddress((void**)&x2h,  g_x2h);
    cudaGetSymbolAddress((void**)&wh1,  g_wh1);
    cudaGetSymbolAddress((void**)&wh2,  g_wh2);
    cudaGetSymbolAddress((void**)&lbt1, g_lbt1);
    cudaGetSymbolAddress((void**)&lbt2, g_lbt2);
    cudaGetSymbolAddress((void**)&lat1, g_lat1);
    cudaGetSymbolAddress((void**)&lat2, g_lat2);
    cudaGetSymbolAddress((void**)&tsh,  g_tsh);
    cudaGetSymbolAddress((void**)&tp,   g_tp);

    constexpr int SMEM = 4 * (2 * 128 * 80) + 512;   // 81920 + 512
    cudaFuncSetAttribute(gemm16<true, true, 64, H_DIM, 16>,
                         cudaFuncAttributeMaxDynamicSharedMemorySize, SMEM);
    cudaFuncSetAttribute(gemm16<false, false, 256, D_DIM, 32>,
                         cudaFuncAttributeMaxDynamicSharedMemorySize, SMEM);

    constexpr int NW = (int)(((size_t)H_DIM * D_DIM / 8) / 256);  // 8192
    constexpr int NX = (int)((M_TOK * (size_t)D_DIM / 8) / 256);  // 8192

    // ---- fused prepasses ----
    prep<<<NX + NW + H_DIM / 256 + D_DIM / 256, 256>>>(
        x1, x1h, NX,
        w_up_q, w_up_sc, wh1, D_DIM, NW,
        w_up_lb, lbt1, H_DIM, H_DIM / 256,
        w_up_la, lat1, D_DIM, D_DIM / 256);
    prep<<<NW + D_DIM / 256 + H_DIM / 256, 256>>>(
        nullptr, nullptr, 0,
        w_dn_q, w_dn_sc, wh2, H_DIM, NW,
        w_dn_lb, lbt2, D_DIM, D_DIM / 256,
        w_dn_la, lat2, H_DIM, H_DIM / 256);

    // ---- layer 1 ----
    lora_mma<<<dim3(M_TOK / 128, 4), 256>>>(x1h, lat1, tp, D_DIM, D_DIM / 4);
    lora_sum<<<128, 256>>>(tp, tsh, 4);
    gemm16<true, true, 64, H_DIM, 16>
        <<<(M_TOK / 128) * (H_DIM / 128), 256, SMEM>>>(
        x1h, wh1, b_up, tsh, lbt1, nullptr, x2h);

    // ---- layer 2 ----
    lora_mma<<<dim3(M_TOK / 128, 8), 256>>>(x2h, lat2, tp, H_DIM, H_DIM / 8);
    lora_sum<<<128, 256>>>(tp, tsh, 8);
    gemm16<false, false, 256, D_DIM, 32>
        <<<(M_TOK / 128) * (D_DIM / 128), 256, SMEM>>>(
        x2h, wh2, b_dn, tsh, lbt2, out, nullptr);
}

// round 13
// speedup vs baseline: 1.3876x; 1.0027x over previous
#include <cuda_runtime.h>
#include <cuda_fp16.h>
#include <cstdint>

#define M_TOK 8192
#define D_DIM 2048
#define H_DIM 8192

// device-global scratch
__device__ __half g_x1h[(size_t)M_TOK * D_DIM];   // x1 -> half
__device__ __half g_x2h[(size_t)M_TOK * H_DIM];   // relu(y1) in half
__device__ __half g_wh1[(size_t)H_DIM * D_DIM];   // dequantized up weights
__device__ __half g_wh2[(size_t)D_DIM * H_DIM];   // dequantized down weights
__device__ __half g_lbt1[(size_t)H_DIM * 32];     // LB1^T padded [N,32]
__device__ __half g_lbt2[(size_t)H_DIM * 32];     // LB2^T padded [N,32]
__device__ __half g_lat1[16 * (size_t)H_DIM];     // lora_a1^T [16,K]
__device__ __half g_lat2[16 * (size_t)H_DIM];     // lora_a2^T [16,K]
__device__ __half g_tsh[(size_t)M_TOK * 32];      // T padded [M,32]
__device__ float  g_tp [8 * (size_t)M_TOK * 16];
__device__ float  g_p1 [(size_t)M_TOK * D_DIM];   // gemm2 split-1 partial

// ---------------------------------------------------------------------------
__device__ __forceinline__ void ldm4(uint32_t* r, uint32_t addr) {
    asm volatile("ldmatrix.sync.aligned.m8n8.x4.shared.b16 {%0,%1,%2,%3}, [%4];"
                 : "=r"(r[0]), "=r"(r[1]), "=r"(r[2]), "=r"(r[3]) : "r"(addr));
}
__device__ __forceinline__ void mma16816(float* d, const uint32_t* a,
                                         uint32_t b0, uint32_t b1) {
    asm volatile("mma.sync.aligned.m16n8k16.row.col.f32.f16.f16.f32 "
                 "{%0,%1,%2,%3}, {%4,%5,%6,%7}, {%8,%9}, {%0,%1,%2,%3};"
                 : "+f"(d[0]), "+f"(d[1]), "+f"(d[2]), "+f"(d[3])
                 : "r"(a[0]), "r"(a[1]), "r"(a[2]), "r"(a[3]), "r"(b0), "r"(b1));
}
__device__ __forceinline__ void cp16(uint32_t dst, const void* src) {
    asm volatile("cp.async.cg.shared.global [%0], [%1], 16;" :: "r"(dst), "l"(src));
}

// ---------------------------------------------------------------------------
// fused prepass: blockIdx ranges -> cvt_x | dq_w | tr_lb | cvt_la
// ---------------------------------------------------------------------------
__global__ __launch_bounds__(256) void prep(
    const float* __restrict__ x, __half* __restrict__ xh, int nx,
    const int* __restrict__ wq, const float* __restrict__ wsc,
    __half* __restrict__ wh, int Kw, int nw,
    const float* __restrict__ lb, __half* __restrict__ lbt, int NT, int nlb,
    const float* __restrict__ la, __half* __restrict__ lat, int Kl, int nla)
{
    const int b = blockIdx.x;
    const int tid = threadIdx.x;

    if (b < nx) {                         // ---- x float -> half
        size_t i = ((size_t)b * 256 + tid) * 8;
        float4 a = *(const float4*)(x + i);
        float4 c = *(const float4*)(x + i + 4);
        __half2 h[4] = {__floats2half2_rn(a.x, a.y), __floats2half2_rn(a.z, a.w),
                        __floats2half2_rn(c.x, c.y), __floats2half2_rn(c.z, c.w)};
        *(uint4*)(xh + i) = *(uint4*)h;
    } else if (b < nx + nw) {             // ---- dequant weights -> half
        size_t i8 = (size_t)(b - nx) * 256 + tid;
        const int K8 = Kw >> 3;
        int row = (int)(i8 / K8), k8 = (int)(i8 % K8);
        float s = wsc[(size_t)row * (Kw >> 6) + (k8 >> 3)];
        int4 q0 = ((const int4*)wq)[i8 * 2];
        int4 q1 = ((const int4*)wq)[i8 * 2 + 1];
        __half2 h[4] = {
            __floats2half2_rn(((float)q0.x - 7.5f) * s, ((float)q0.y - 7.5f) * s),
            __floats2half2_rn(((float)q0.z - 7.5f) * s, ((float)q0.w - 7.5f) * s),
            __floats2half2_rn(((float)q1.x - 7.5f) * s, ((float)q1.y - 7.5f) * s),
            __floats2half2_rn(((float)q1.z - 7.5f) * s, ((float)q1.w - 7.5f) * s)};
        *(uint4*)(wh + i8 * 8) = *(uint4*)h;
    } else if (b < nx + nw + nlb) {       // ---- LB^T padded [N,32]
        int n = (b - nx - nw) * 256 + tid;
        __half2 h[16];
#pragma unroll
        for (int r = 0; r < 8; r++)
            h[r] = __floats2half2_rn(lb[(size_t)(2 * r) * NT + n],
                                     lb[(size_t)(2 * r + 1) * NT + n]);
#pragma unroll
        for (int r = 8; r < 16; r++) h[r] = __floats2half2_rn(0.f, 0.f);
#pragma unroll
        for (int c = 0; c < 4; c++)
            *(uint4*)(lbt + (size_t)n * 32 + c * 8) = ((uint4*)h)[c];
    } else {                              // ---- lora_a [K,16] -> At [16,K]
        __shared__ __half s[16][264];
        const int k0 = (b - nx - nw - nlb) * 256;
#pragma unroll
        for (int q = 0; q < 4; q++) {
            float4 v = *(const float4*)(la + (size_t)(k0 + tid) * 16 + q * 4);
            s[q * 4 + 0][tid] = __float2half_rn(v.x);
            s[q * 4 + 1][tid] = __float2half_rn(v.y);
            s[q * 4 + 2][tid] = __float2half_rn(v.z);
            s[q * 4 + 3][tid] = __float2half_rn(v.w);
        }
        __syncthreads();
#pragma unroll
        for (int rep = 0; rep < 2; rep++) {
            int idx = tid + 256 * rep;
            int r = idx >> 5, c = idx & 31;
            *(uint4*)(lat + (size_t)r * Kl + k0 + c * 8) = *(uint4*)&s[r][c * 8];
        }
    }
}

// ---------------------------------------------------------------------------
// LoRA via tensor core (R9-proven): Tp[split][m][r] = X @ At^T on a k-chunk
// ---------------------------------------------------------------------------
__global__ __launch_bounds__(256) void lora_mma(const __half* __restrict__ X,
                                                const __half* __restrict__ At,
                                                float* __restrict__ Tp,
                                                int K, int KC)
{
    constexpr int PITCH = 80;
    constexpr int XSZ = 128 * PITCH;
    constexpr int BSZ = 16 * PITCH;
    constexpr int STG = XSZ + BSZ;
    constexpr int NST = 4;
    __shared__ __align__(16) char smem[NST * STG];
    uint32_t sbase;
    asm("{ .reg .u64 t; cvta.to.shared.u64 t, %1; cvt.u32.u64 %0, t; }"
        : "=r"(sbase) : "l"(smem));

    const int tid = threadIdx.x, lane = tid & 31, w = tid >> 5;
    const int lr = lane >> 2, lc = lane & 3;
    const int m0 = blockIdx.x * 128;
    const int k0 = blockIdx.y * KC;
    const int TOT = KC / 32;

    const int frow = tid >> 1;
    const int fc0 = (tid & 1) * 2;

    auto FILL = [&](int it) {
        if (it < TOT) {
            const uint32_t st = sbase + (uint32_t)(it & (NST - 1)) * STG;
            const int k = k0 + it * 32;
#pragma unroll
            for (int j = 0; j < 2; j++) {
                int c = fc0 + j;
                cp16(st + (uint32_t)(frow * PITCH + c * 16),
                     X + (size_t)(m0 + frow) * K + k + c * 8);
            }
            if (tid < 64) {
                int r = tid >> 2, c = tid & 3;
                cp16(st + (uint32_t)(XSZ + r * PITCH + c * 16),
                     At + (size_t)r * K + k + c * 8);
            }
        }
        asm volatile("cp.async.commit_group;" ::: "memory");
    };

    float acc[2][4];
#pragma unroll
    for (int i = 0; i < 2; i++)
#pragma unroll
        for (int j = 0; j < 4; j++) acc[i][j] = 0.f;

#pragma unroll
    for (int p = 0; p < NST - 1; ++p) FILL(p);

    const int arow = w * 16 + (lane & 15);
    const int asel = lane >> 4;
    const int brow = ((lane >> 4) << 3) + (lane & 7);
    const int bsel = (lane >> 3) & 1;

    for (int it = 0; it < TOT; ++it) {
        asm volatile("cp.async.wait_group %0;" :: "n"(NST - 2) : "memory");
        __syncthreads();
        const uint32_t sA = sbase + (uint32_t)(it & (NST - 1)) * STG;
        const uint32_t sB = sA + XSZ;
#pragma unroll
        for (int ks = 0; ks < 2; ks++) {
            uint32_t a[4], b[4];
            ldm4(a, sA + (uint32_t)(arow * PITCH + (ks * 2 + asel) * 16));
            ldm4(b, sB + (uint32_t)(brow * PITCH + (ks * 2 + bsel) * 16));
            mma16816(acc[0], a, b[0], b[1]);
            mma16816(acc[1], a, b[2], b[3]);
        }
        FILL(it + NST - 1);
    }

    float* o = Tp + (size_t)blockIdx.y * (M_TOK * 16);
    const int m = m0 + 16 * w + lr;
#pragma unroll
    for (int nt = 0; nt < 2; nt++) {
        const int col = 8 * nt + 2 * lc;
        *(float2*)(o + (size_t)m * 16 + col)       = make_float2(acc[nt][0], acc[nt][1]);
        *(float2*)(o + (size_t)(m + 8) * 16 + col) = make_float2(acc[nt][2], acc[nt][3]);
    }
}

__global__ __launch_bounds__(256) void lora_sum(const float* __restrict__ Tp,
                                                __half* __restrict__ Ts, int split)
{
    const int i = blockIdx.x * 256 + threadIdx.x;
    const int m = i >> 2, rq = i & 3;
    const float4* p = (const float4*)Tp;
    float4 a = p[i];
    for (int s = 1; s < split; s++) {
        float4 b = p[i + (size_t)s * 32768];
        a.x += b.x; a.y += b.y; a.z += b.z; a.w += b.w;
    }
    __half2 h[2] = {__floats2half2_rn(a.x, a.y), __floats2half2_rn(a.z, a.w)};
    *(uint2*)(Ts + (size_t)m * 32 + rq * 4) = *(uint2*)h;
    *(uint2*)(Ts + (size_t)m * 32 + 16 + rq * 4) = make_uint2(0u, 0u);
}

// ---------------------------------------------------------------------------
// fp16 mma GEMM (R9-proven, frozen): CTA 128x128, BK=32, 256 thr,
// 4-stage cp.async ring, pitch-80 smem, LoRA folded as one extra k-tile.
// ---------------------------------------------------------------------------
template<bool RELU, bool STORE_HALF, int KTILES, int NT, int GROUP>
__global__ __launch_bounds__(256, 2) void gemm16(
    const __half* __restrict__ Xh, const __half* __restrict__ Wh,
    const float* __restrict__ bias,
    const __half* __restrict__ Tsh, const __half* __restrict__ LBTh,
    float* __restrict__ Yf, __half* __restrict__ Yh)
{
    constexpr int K   = KTILES * 32;
    constexpr int NTILES = NT / 128;
    constexpr int TOT = KTILES + 1;
    constexpr int PITCH = 80;
    constexpr int ASZ = 128 * PITCH;
    constexpr int STG = 2 * ASZ;
    constexpr int NST = 4;

    extern __shared__ __align__(16) char smem[];
    float* sbias = (float*)(smem + NST * STG);
    uint32_t sbase;
    asm("{ .reg .u64 t; cvta.to.shared.u64 t, %1; cvt.u32.u64 %0, t; }"
        : "=r"(sbase) : "l"(smem));

    const int tid  = threadIdx.x;
    const int lane = tid & 31;
    const int wid  = tid >> 5;
    const int wm = wid & 3, wn = wid >> 2;
    const int lr = lane >> 2, lc = lane & 3;

    constexpr int NPG = GROUP * NTILES;
    const int pid = blockIdx.x;
    const int grp = pid / NPG, rem = pid % NPG;
    const int bm0 = (grp * GROUP + rem % GROUP) * 128;
    const int bn0 = (rem / GROUP) * 128;

    if (tid < 128) sbias[tid] = bias[bn0 + tid];

    const int frow = tid >> 1;
    const int fc0  = (tid & 1) * 2;

    auto FILL = [&](int it) {
        if (it < TOT) {
            const uint32_t st = sbase + (uint32_t)(it % NST) * STG;
            const bool mn = (it < KTILES);
            const int k0 = it * 32;
#pragma unroll
            for (int c = fc0; c < fc0 + 2; c++) {
                const __half* ga = mn ? Xh + (size_t)(bm0 + frow) * K + k0 + c * 8
                                      : Tsh + (size_t)(bm0 + frow) * 32 + c * 8;
                const __half* gb = mn ? Wh + (size_t)(bn0 + frow) * K + k0 + c * 8
                                      : LBTh + (size_t)(bn0 + frow) * 32 + c * 8;
                cp16(st + (uint32_t)(frow * PITCH + c * 16), ga);
                cp16(st + (uint32_t)(ASZ + frow * PITCH + c * 16), gb);
            }
        }
        asm volatile("cp.async.commit_group;" ::: "memory");
    };

    float acc[2][8][4];
#pragma unroll
    for (int i = 0; i < 2; i++)
#pragma unroll
        for (int j = 0; j < 8; j++)
#pragma unroll
            for (int k = 0; k < 4; k++) acc[i][j][k] = 0.f;

#pragma unroll
    for (int p = 0; p < NST - 1; ++p) FILL(p);

    const int arow = wm * 32 + (lane & 15);
    const int asel = lane >> 4;
    const int brow = wn * 64 + ((lane >> 4) << 3) + (lane & 7);
    const int bsel = (lane >> 3) & 1;

    for (int it = 0; it < TOT; ++it) {
        asm volatile("cp.async.wait_group %0;" :: "n"(NST - 2) : "memory");
        __syncthreads();

        const uint32_t sA = sbase + (uint32_t)(it % NST) * STG;
        const uint32_t sB = sA + ASZ;
#pragma unroll
        for (int ks = 0; ks < 2; ks++) {
            uint32_t a[2][4];
#pragma unroll
            for (int mt = 0; mt < 2; mt++)
                ldm4(a[mt], sA + (uint32_t)((arow + mt * 16) * PITCH
                                            + (ks * 2 + asel) * 16));
#pragma unroll
            for (int np = 0; np < 4; np++) {
                uint32_t b[4];
                ldm4(b, sB + (uint32_t)((brow + np * 16) * PITCH
                                        + (ks * 2 + bsel) * 16));
#pragma unroll
                for (int mt = 0; mt < 2; mt++) {
                    mma16816(acc[mt][2 * np],     a[mt], b[0], b[1]);
                    mma16816(acc[mt][2 * np + 1], a[mt], b[2], b[3]);
                }
            }
        }
        FILL(it + NST - 1);
    }

#pragma unroll
    for (int mt = 0; mt < 2; mt++) {
        const int m = bm0 + 32 * wm + 16 * mt + lr;
#pragma unroll
        for (int nt = 0; nt < 8; nt++) {
            const int ncol = 64 * wn + 8 * nt + 2 * lc;
            const float b0 = sbias[ncol], b1 = sbias[ncol + 1];
            float v0 = acc[mt][nt][0] + b0, v1 = acc[mt][nt][1] + b1;
            float v2 = acc[mt][nt][2] + b0, v3 = acc[mt][nt][3] + b1;
            if (RELU) {
                v0 = fmaxf(v0, 0.f); v1 = fmaxf(v1, 0.f);
                v2 = fmaxf(v2, 0.f); v3 = fmaxf(v3, 0.f);
            }
            if (STORE_HALF) {
                *(__half2*)(Yh + (size_t)m * NT + bn0 + ncol) =
                    __floats2half2_rn(v0, v1);
                *(__half2*)(Yh + (size_t)(m + 8) * NT + bn0 + ncol) =
                    __floats2half2_rn(v2, v3);
            } else {
                *(float2*)(Yf + (size_t)m * NT + bn0 + ncol)       = make_float2(v0, v1);
                *(float2*)(Yf + (size_t)(m + 8) * NT + bn0 + ncol) = make_float2(v2, v3);
            }
        }
    }
}

// ---------------------------------------------------------------------------
// GEMM2 split-K=2: one launch, grid 2048. split=pid>>10 picks K half.
// Split 0: k[0,4096) + lora tile + bias -> out. Split 1: k[4096,8192) -> p1.
// Mainloop body identical to gemm16.
// ---------------------------------------------------------------------------
__global__ __launch_bounds__(256, 2) void gemm16sk(
    const __half* __restrict__ Xh, const __half* __restrict__ Wh,
    const float* __restrict__ bias,
    const __half* __restrict__ Tsh, const __half* __restrict__ LBTh,
    float* __restrict__ Yout, float* __restrict__ Ypart)
{
    constexpr int KF  = H_DIM;            // full K = 8192
    constexpr int KT  = 128;              // k-tiles per split
    constexpr int NT  = D_DIM;
    constexpr int PITCH = 80;
    constexpr int ASZ = 128 * PITCH;
    constexpr int STG = 2 * ASZ;
    constexpr int NST = 4;
    constexpr int GROUP = 16, NTILES = NT / 128, NPG = GROUP * NTILES;

    extern __shared__ __align__(16) char smem[];
    float* sbias = (float*)(smem + NST * STG);
    uint32_t sbase;
    asm("{ .reg .u64 t; cvta.to.shared.u64 t, %1; cvt.u32.u64 %0, t; }"
        : "=r"(sbase) : "l"(smem));

    const int tid  = threadIdx.x;
    const int lane = tid & 31;
    const int wid  = tid >> 5;
    const int wm = wid & 3, wn = wid >> 2;
    const int lr = lane >> 2, lc = lane & 3;

    const int pid = blockIdx.x;
    const int split = pid >> 10;
    const int pl = pid & 1023;
    const int koff = split << 12;         // 0 or 4096
    const int TOT = KT + (split ? 0 : 1); // lora tile only in split 0

    const int grp = pl / NPG, rem = pl % NPG;
    const int bm0 = (grp * GROUP + rem % GROUP) * 128;
    const int bn0 = (rem / GROUP) * 128;

    if (tid < 128) sbias[tid] = bias[bn0 + tid];

    const int frow = tid >> 1;
    const int fc0  = (tid & 1) * 2;

    auto FILL = [&](int it) {
        if (it < TOT) {
            const uint32_t st = sbase + (uint32_t)(it % NST) * STG;
            const bool mn = (it < KT);
            const int k0 = koff + it * 32;
#pragma unroll
            for (int c = fc0; c < fc0 + 2; c++) {
                const __half* ga = mn ? Xh + (size_t)(bm0 + frow) * KF + k0 + c * 8
                                      : Tsh + (size_t)(bm0 + frow) * 32 + c * 8;
                const __half* gb = mn ? Wh + (size_t)(bn0 + frow) * KF + k0 + c * 8
                                      : LBTh + (size_t)(bn0 + frow) * 32 + c * 8;
                cp16(st + (uint32_t)(frow * PITCH + c * 16), ga);
                cp16(st + (uint32_t)(ASZ + frow * PITCH + c * 16), gb);
            }
        }
        asm volatile("cp.async.commit_group;" ::: "memory");
    };

    float acc[2][8][4];
#pragma unroll
    for (int i = 0; i < 2; i++)
#pragma unroll
        for (int j = 0; j < 8; j++)
#pragma unroll
            for (int k = 0; k < 4; k++) acc[i][j][k] = 0.f;

#pragma unroll
    for (int p = 0; p < NST - 1; ++p) FILL(p);

    const int arow = wm * 32 + (lane & 15);
    const int asel = lane >> 4;
    const int brow = wn * 64 + ((lane >> 4) << 3) + (lane & 7);
    const int bsel = (lane >> 3) & 1;

    for (int it = 0; it < TOT; ++it) {
        asm volatile("cp.async.wait_group %0;" :: "n"(NST - 2) : "memory");
        __syncthreads();

        const uint32_t sA = sbase + (uint32_t)(it % NST) * STG;
        const uint32_t sB = sA + ASZ;
#pragma unroll
        for (int ks = 0; ks < 2; ks++) {
            uint32_t a[2][4];
#pragma unroll
            for (int mt = 0; mt < 2; mt++)
                ldm4(a[mt], sA + (uint32_t)((arow + mt * 16) * PITCH
                                            + (ks * 2 + asel) * 16));
#pragma unroll
            for (int np = 0; np < 4; np++) {
                uint32_t b[4];
                ldm4(b, sB + (uint32_t)((brow + np * 16) * PITCH
                                        + (ks * 2 + bsel) * 16));
#pragma unroll
                for (int mt = 0; mt < 2; mt++) {
                    mma16816(acc[mt][2 * np],     a[mt], b[0], b[1]);
                    mma16816(acc[mt][2 * np + 1], a[mt], b[2], b[3]);
                }
            }
        }
        FILL(it + NST - 1);
    }

    float* Y = split ? Ypart : Yout;
#pragma unroll
    for (int mt = 0; mt < 2; mt++) {
        const int m = bm0 + 32 * wm + 16 * mt + lr;
#pragma unroll
        for (int nt = 0; nt < 8; nt++) {
            const int ncol = 64 * wn + 8 * nt + 2 * lc;
            float v0 = acc[mt][nt][0], v1 = acc[mt][nt][1];
            float v2 = acc[mt][nt][2], v3 = acc[mt][nt][3];
            if (split == 0) {
                const float b0 = sbias[ncol], b1 = sbias[ncol + 1];
                v0 += b0; v1 += b1; v2 += b0; v3 += b1;
            }
            *(float2*)(Y + (size_t)m * NT + bn0 + ncol)       = make_float2(v0, v1);
            *(float2*)(Y + (size_t)(m + 8) * NT + bn0 + ncol) = make_float2(v2, v3);
        }
    }
}

// out += p1 (vectorized)
__global__ __launch_bounds__(256) void red_add(float* __restrict__ out,
                                               const float* __restrict__ p)
{
    size_t i = (size_t)blockIdx.x * 256 + threadIdx.x;
    float4 a = ((const float4*)out)[i];
    float4 b = ((const float4*)p)[i];
    ((float4*)out)[i] = make_float4(a.x + b.x, a.y + b.y, a.z + b.z, a.w + b.w);
}

// ---------------------------------------------------------------------------
extern "C" void kernel_launch(void* const* d_in, const int* in_sizes, int n_in,
                              void* d_out, int out_size)
{
    const float* x1      = (const float*)d_in[0];
    const int*   w_up_q  = (const int*)  d_in[1];
    const float* w_up_sc = (const float*)d_in[2];
    const float* b_up    = (const float*)d_in[3];
    const float* w_up_la = (const float*)d_in[4];
    const float* w_up_lb = (const float*)d_in[5];
    const int*   w_dn_q  = (const int*)  d_in[6];
    const float* w_dn_sc = (const float*)d_in[7];
    const float* b_dn    = (const float*)d_in[8];
    const float* w_dn_la = (const float*)d_in[9];
    const float* w_dn_lb = (const float*)d_in[10];
    float*       out     = (float*)d_out;

    __half *x1h, *x2h, *wh1, *wh2, *lbt1, *lbt2, *lat1, *lat2, *tsh;
    float *tp, *p1;
    cudaGetSymbolAddress((void**)&x1h,  g_x1h);
    cudaGetSymbolAddress((void**)&x2h,  g_x2h);
    cudaGetSymbolAddress((void**)&wh1,  g_wh1);
    cudaGetSymbolAddress((void**)&wh2,  g_wh2);
    cudaGetSymbolAddress((void**)&lbt1, g_lbt1);
    cudaGetSymbolAddress((void**)&lbt2, g_lbt2);
    cudaGetSymbolAddress((void**)&lat1, g_lat1);
    cudaGetSymbolAddress((void**)&lat2, g_lat2);
    cudaGetSymbolAddress((void**)&tsh,  g_tsh);
    cudaGetSymbolAddress((void**)&tp,   g_tp);
    cudaGetSymbolAddress((void**)&p1,   g_p1);

    constexpr int SMEM = 4 * (2 * 128 * 80) + 512;   // 81920 + 512
    cudaFuncSetAttribute(gemm16<true, true, 64, H_DIM, 16>,
                         cudaFuncAttributeMaxDynamicSharedMemorySize, SMEM);
    cudaFuncSetAttribute(gemm16sk,
                         cudaFuncAttributeMaxDynamicSharedMemorySize, SMEM);

    constexpr int NW = (int)(((size_t)H_DIM * D_DIM / 8) / 256);  // 8192
    constexpr int NX = (int)((M_TOK * (size_t)D_DIM / 8) / 256);  // 8192

    // ---- fused prepasses ----
    prep<<<NX + NW + H_DIM / 256 + D_DIM / 256, 256>>>(
        x1, x1h, NX,
        w_up_q, w_up_sc, wh1, D_DIM, NW,
        w_up_lb, lbt1, H_DIM, H_DIM / 256,
        w_up_la, lat1, D_DIM, D_DIM / 256);
    prep<<<NW + D_DIM / 256 + H_DIM / 256, 256>>>(
        nullptr, nullptr, 0,
        w_dn_q, w_dn_sc, wh2, H_DIM, NW,
        w_dn_lb, lbt2, D_DIM, D_DIM / 256,
        w_dn_la, lat2, H_DIM, H_DIM / 256);

    // ---- layer 1 ----
    lora_mma<<<dim3(M_TOK / 128, 4), 256>>>(x1h, lat1, tp, D_DIM, D_DIM / 4);
    lora_sum<<<128, 256>>>(tp, tsh, 4);
    gemm16<true, true, 64, H_DIM, 16>
        <<<(M_TOK / 128) * (H_DIM / 128), 256, SMEM>>>(
        x1h, wh1, b_up, tsh, lbt1, nullptr, x2h);

    // ---- layer 2 (split-K=2) ----
    lora_mma<<<dim3(M_TOK / 128, 8), 256>>>(x2h, lat2, tp, H_DIM, H_DIM / 8);
    lora_sum<<<128, 256>>>(tp, tsh, 8);
    gemm16sk<<<2 * (M_TOK / 128) * (D_DIM / 128), 256, SMEM>>>(
        x2h, wh2, b_dn, tsh, lbt2, out, p1);
    red_add<<<(int)((size_t)M_TOK * D_DIM / 4 / 256), 256>>>(out, p1);
}